// round 16
// baseline (speedup 1.0000x reference)
#include <cuda_runtime.h>
#include <cuda_fp16.h>
#include <cstdint>

#define N_  32768
#define NZ_ 512
#define H_  1024
#define C_  128
#define K_  8
#define TPB 512
#define BM  128          // rows per CTA
#define BH  128          // h columns per chunk
#define KS  64           // K depth per stage (fp16: 128B rows)
#define PITB 144         // staging row pitch bytes (128B data + 16 pad)
#define LDHH 136         // hs pitch in halves (272B = 256 data + 16 pad)

// ---------------- device scratch (static globals: allowed) -----------------
__device__ float  g_q[N_ * K_];
__device__ __half g_zth[N_ * NZ_];         // fp16 z
__device__ __half g_w1th[K_ * H_ * NZ_];   // [K][H][NZ]  n-major fp16
__device__ __half g_w2th[K_ * C_ * H_];    // [K][C][H]   n-major fp16

// ---------------- helpers ---------------------------------------------------
__device__ __forceinline__ uint32_t smem_u32(const void* p) {
    uint32_t a;
    asm("{ .reg .u64 t; cvta.to.shared.u64 t, %1; cvt.u32.u64 %0, t; }" : "=r"(a) : "l"(p));
    return a;
}
__device__ __forceinline__ void cp16(uint32_t s, const void* g) {
    asm volatile("cp.async.cg.shared.global [%0], [%1], 16;" :: "r"(s), "l"(g) : "memory");
}
#define CP_COMMIT() asm volatile("cp.async.commit_group;" ::: "memory")
#define CP_WAIT2()  asm volatile("cp.async.wait_group 2;" ::: "memory")

__device__ __forceinline__ void ldsm4(uint32_t* r, uint32_t a) {
    asm volatile("ldmatrix.sync.aligned.m8n8.x4.shared.b16 {%0,%1,%2,%3}, [%4];"
                 : "=r"(r[0]), "=r"(r[1]), "=r"(r[2]), "=r"(r[3]) : "r"(a));
}

// m16n8k16 fp16 mma, fp32 accum. A row-major (4 regs), B col-major [n][k] (2 regs)
__device__ __forceinline__ void mma16(float* c, const uint32_t* a, uint32_t b0, uint32_t b1) {
    asm volatile(
        "mma.sync.aligned.m16n8k16.row.col.f32.f16.f16.f32 "
        "{%0,%1,%2,%3}, {%4,%5,%6,%7}, {%8,%9}, {%0,%1,%2,%3};"
        : "+f"(c[0]), "+f"(c[1]), "+f"(c[2]), "+f"(c[3])
        : "r"(a[0]), "r"(a[1]), "r"(a[2]), "r"(a[3]), "r"(b0), "r"(b1));
}

// ---------------------------------------------------------------------------
// prep_kernel: z->fp16, W1/W2 transpose->fp16 n-major, q.  One kernel.
// ---------------------------------------------------------------------------
#define PREP_TPB 256
#define NB_Z  16384
#define NB_T1 4096
#define NB_T2 1024
#define NB_Q  4096

__global__ void prep_kernel(const float* __restrict__ z, const float* __restrict__ mu,
                            const float* __restrict__ W1, const float* __restrict__ W2) {
    __shared__ float t[32][33];
    __shared__ float smu[K_ * NZ_];
    const int bid = blockIdx.x;
    const int tid = threadIdx.x;

    if (bid < NB_Z) {
        int i = bid * PREP_TPB + tid;      // float4 index
        float4 v = ((const float4*)z)[i];
        __half2* dst = (__half2*)g_zth;
        dst[2 * i]     = __floats2half2_rn(v.x, v.y);
        dst[2 * i + 1] = __floats2half2_rn(v.z, v.w);
        return;
    }
    if (bid < NB_Z + NB_T1) {              // W1 [K,NZ,H] -> g_w1th [K,H,NZ]
        int i = bid - NB_Z;
        int xx = i & 31, yy = (i >> 5) & 15, b = i >> 9;
        int r0 = yy * 32, c0 = xx * 32;
        const float* s = W1 + (size_t)b * NZ_ * H_;
        __half* d = g_w1th + (size_t)b * NZ_ * H_;
        int tx = tid & 31, ty = tid >> 5;
#pragma unroll
        for (int ii = 0; ii < 32; ii += 8)
            t[ty + ii][tx] = s[(size_t)(r0 + ty + ii) * H_ + c0 + tx];
        __syncthreads();
#pragma unroll
        for (int ii = 0; ii < 32; ii += 8)
            d[(size_t)(c0 + ty + ii) * NZ_ + r0 + tx] = __float2half_rn(t[tx][ty + ii]);
        return;
    }
    if (bid < NB_Z + NB_T1 + NB_T2) {      // W2 [K,H,C] -> g_w2th [K,C,H]
        int i = bid - NB_Z - NB_T1;
        int xx = i & 3, yy = (i >> 2) & 31, b = i >> 7;
        int r0 = yy * 32, c0 = xx * 32;
        const float* s = W2 + (size_t)b * H_ * C_;
        __half* d = g_w2th + (size_t)b * H_ * C_;
        int tx = tid & 31, ty = tid >> 5;
#pragma unroll
        for (int ii = 0; ii < 32; ii += 8)
            t[ty + ii][tx] = s[(size_t)(r0 + ty + ii) * C_ + c0 + tx];
        __syncthreads();
#pragma unroll
        for (int ii = 0; ii < 32; ii += 8)
            d[(size_t)(c0 + ty + ii) * H_ + r0 + tx] = __float2half_rn(t[tx][ty + ii]);
        return;
    }
    {   // q
        int qb = bid - NB_Z - NB_T1 - NB_T2;
        for (int i = tid; i < K_ * NZ_; i += PREP_TPB) smu[i] = mu[i];
        __syncthreads();
        int gwarp = (qb * PREP_TPB + tid) >> 5;
        int lane  = tid & 31;
        if (gwarp >= N_) return;
        const float* zr = z + (size_t)gwarp * NZ_;
        float acc[K_];
#pragma unroll
        for (int k = 0; k < K_; k++) acc[k] = 0.f;
        for (int j = lane; j < NZ_; j += 32) {
            float zj = zr[j];
#pragma unroll
            for (int k = 0; k < K_; k++) {
                float d = zj - smu[k * NZ_ + j];
                acc[k] = fmaf(d, d, acc[k]);
            }
        }
#pragma unroll
        for (int k = 0; k < K_; k++)
#pragma unroll
            for (int o = 16; o > 0; o >>= 1)
                acc[k] += __shfl_xor_sync(0xffffffffu, acc[k], o);
        if (lane == 0) {
            float w[K_], s = 0.f;
#pragma unroll
            for (int k = 0; k < K_; k++) { w[k] = 1.f / (1.f + acc[k]); s += w[k]; }
            float inv = 1.f / s;
#pragma unroll
            for (int k = 0; k < K_; k++) g_q[gwarp * K_ + k] = w[k] * inv;
        }
    }
}

// ---------------------------------------------------------------------------
// fused fp16 mma: continuous cp.async ring (no exposed waits).
//  - 4-stage W1 ring spans chunk boundaries (next chunk prefetched at s=5..7)
//  - W2 staged into dedicated buffers inside the s=0 commit group
//  - exactly ONE commit group per GEMM1 iteration -> uniform wait_group 2
// ---------------------------------------------------------------------------
#define STG_BYTES (2 * 128 * PITB)            // A 18432 + B 18432 = 36864
#define OFF_W2    (4 * STG_BYTES)             // 147456 (2 x 128*PITB = 36864)
#define OFF_HS    (OFF_W2 + 2 * 128 * PITB)   // 184320
#define OFF_B2S   (OFF_HS + 128 * LDHH * 2)   // 219136
#define OFF_B1S   (OFF_B2S + 4096)            // 223232
#define SMEM_DYN  (OFF_B1S + 512)             // 223744  (< 227KB cap)

// stage subtile ss of GEMM1 (z + W1 rows hti..hti+127 of wb) into stage st
#define ISSUE1X(wb_, hti_, ss_, st_) do {                                     \
    const int zb_ = (ss_) * KS;                                               \
    const uint32_t ua_ = uST[st_];                                            \
    const uint32_t ub_ = uST[st_] + 128 * PITB;                               \
    _Pragma("unroll")                                                         \
    for (int v = 0; v < 2; v++) {                                             \
        int lin = tid + v * TPB;                                              \
        int row = lin >> 3, seg = lin & 7;                                    \
        cp16(ua_ + row * PITB + seg * 16,                                     \
             g_zth + (size_t)(n0 + row) * NZ_ + zb_ + seg * 8);               \
    }                                                                         \
    _Pragma("unroll")                                                         \
    for (int v = 0; v < 2; v++) {                                             \
        int lin = tid + v * TPB;                                              \
        int row = lin >> 3, seg = lin & 7;                                    \
        cp16(ub_ + row * PITB + seg * 16,                                     \
             (wb_) + (size_t)((hti_) + row) * NZ_ + zb_ + seg * 8);           \
    }                                                                         \
} while (0)

// stage BOTH W2 subtiles (cols ht..ht+127) into the two dedicated buffers
#define ISSUEW2() do {                                                        \
    _Pragma("unroll")                                                         \
    for (int v = 0; v < 4; v++) {                                             \
        int lin = tid + v * TPB;            /* 0..2047 */                     \
        int j   = lin >> 10;                /* buffer 0/1 */                  \
        int r2  = (lin >> 3) & 127;                                           \
        int seg = lin & 7;                                                    \
        cp16(uW2 + j * (128 * PITB) + r2 * PITB + seg * 16,                   \
             w2base + (size_t)r2 * H_ + ht + j * KS + seg * 8);               \
    }                                                                         \
} while (0)

__global__ void __launch_bounds__(TPB, 1) fused_mma(
    const float* __restrict__ b1, const float* __restrict__ b2,
    float* __restrict__ out)
{
    extern __shared__ char sm[];
    __half* const hs  = (__half*)(sm + OFF_HS);
    float*  const b2s = (float*)(sm + OFF_B2S);
    float*  const b1s = (float*)(sm + OFF_B1S);

    const uint32_t sb = smem_u32(sm);
    const uint32_t uST[4] = { sb, sb + STG_BYTES, sb + 2 * STG_BYTES, sb + 3 * STG_BYTES };
    const uint32_t uW2 = sb + OFF_W2;
    const uint32_t uHS = sb + OFF_HS;

    const int tid  = threadIdx.x;
    const int lane = tid & 31;
    const int warp = tid >> 5;       // 0..15
    const int wm   = warp & 3;       // row block of 32
    const int wn   = warp >> 2;      // col block of 32
    const int gr   = lane >> 2;      // 0..7
    const int tig  = lane & 3;       // 0..3
    const int rbase = wm * 32;
    const int cbase = wn * 32;
    const int n0   = blockIdx.x * BM;

    // ldmatrix lane offsets (bytes)
    const int lr = lane & 7;
    const int lg = lane >> 3;
    const uint32_t aOffT = (uint32_t)((lr + (lg & 1) * 8) * PITB + (lg >> 1) * 16);
    const uint32_t aOffH = (uint32_t)((lr + (lg & 1) * 8) * (LDHH * 2) + (lg >> 1) * 16);
    const uint32_t bOffT = (uint32_t)((lr + (lg >> 1) * 8) * PITB + (lg & 1) * 16);

    for (int i = tid; i < K_ * C_; i += TPB) b2s[i] = b2[i];

    float outacc[32];
#pragma unroll
    for (int i = 0; i < 32; i++) outacc[i] = 0.f;

    // bootstrap: first chunk's subtiles 0..2
    {
        const __half* wb0 = g_w1th;
        ISSUE1X(wb0, 0, 0, 0); CP_COMMIT();
        ISSUE1X(wb0, 0, 1, 1); CP_COMMIT();
        ISSUE1X(wb0, 0, 2, 2); CP_COMMIT();
    }

    for (int k = 0; k < K_; k++) {
        const __half* w1base = g_w1th + (size_t)k * H_ * NZ_;
        const __half* w2base = g_w2th + (size_t)k * C_ * H_;

        for (int ht = 0; ht < H_; ht += BH) {
            // next-chunk coordinates for the cross-boundary prefetch
            int ht2 = ht + BH, k2 = k;
            const __half* w1b2 = w1base;
            if (ht2 == H_) { ht2 = 0; k2 = k + 1; w1b2 = w1base + (size_t)H_ * NZ_; }
            const bool nvalid = (k2 < K_);

            __syncthreads();   // prev chunk epilogue/GEMM2 fully done
            if (tid < BH) b1s[tid] = b1[k * H_ + ht + tid];

            float hacc[32];
#pragma unroll
            for (int i = 0; i < 32; i++) hacc[i] = 0.f;

            // ===== GEMM1: 8 subtiles; one commit group per iteration =======
            for (int s = 0; s < 8; s++) {
                const int st = s & 3;
                CP_WAIT2();
                __syncthreads();
                if (s < 5)        { ISSUE1X(w1base, ht, s + 3, (s + 3) & 3); }
                else if (nvalid)  { ISSUE1X(w1b2, ht2, s - 5, (s - 5) & 3); }
                if (s == 0)       { ISSUEW2(); }
                CP_COMMIT();
#pragma unroll
                for (int kk = 0; kk < 4; kk++) {
                    uint32_t a0[4], a1[4], bb0[4], bb1[4];
                    const uint32_t ab = uST[st] + (uint32_t)(kk * 32);
                    ldsm4(a0, ab + (uint32_t)(rbase * PITB) + aOffT);
                    ldsm4(a1, ab + (uint32_t)((rbase + 16) * PITB) + aOffT);
                    const uint32_t bbse = uST[st] + (uint32_t)(128 * PITB) + (uint32_t)(kk * 32);
                    ldsm4(bb0, bbse + (uint32_t)(cbase * PITB) + bOffT);
                    ldsm4(bb1, bbse + (uint32_t)((cbase + 16) * PITB) + bOffT);
                    mma16(&hacc[0],  a0, bb0[0], bb0[1]);
                    mma16(&hacc[4],  a0, bb0[2], bb0[3]);
                    mma16(&hacc[8],  a0, bb1[0], bb1[1]);
                    mma16(&hacc[12], a0, bb1[2], bb1[3]);
                    mma16(&hacc[16], a1, bb0[0], bb0[1]);
                    mma16(&hacc[20], a1, bb0[2], bb0[3]);
                    mma16(&hacc[24], a1, bb1[0], bb1[1]);
                    mma16(&hacc[28], a1, bb1[2], bb1[3]);
                }
            }

            // ---- hs = fp16(q * relu(hacc + b1)) ----
#pragma unroll
            for (int tm = 0; tm < 2; tm++) {
                int r0 = rbase + tm * 16 + gr;
                float qa = g_q[(size_t)(n0 + r0) * K_ + k];
                float qb = g_q[(size_t)(n0 + r0 + 8) * K_ + k];
#pragma unroll
                for (int tn = 0; tn < 4; tn++) {
                    int idx = (tm * 16 + tn * 4);
                    int c0  = cbase + tn * 8 + 2 * tig;
                    float va0 = fmaxf(hacc[idx + 0] + b1s[c0], 0.f) * qa;
                    float va1 = fmaxf(hacc[idx + 1] + b1s[c0 + 1], 0.f) * qa;
                    float vb0 = fmaxf(hacc[idx + 2] + b1s[c0], 0.f) * qb;
                    float vb1 = fmaxf(hacc[idx + 3] + b1s[c0 + 1], 0.f) * qb;
                    *(__half2*)&hs[r0 * LDHH + c0]       = __floats2half2_rn(va0, va1);
                    *(__half2*)&hs[(r0 + 8) * LDHH + c0] = __floats2half2_rn(vb0, vb1);
                }
            }
            __syncthreads();   // hs visible (W2 landed long ago: group s=0)

            // ===== GEMM2: 2 subtiles of 64, NO waits ========================
#pragma unroll
            for (int s = 0; s < 2; s++) {
#pragma unroll
                for (int kk = 0; kk < 4; kk++) {
                    uint32_t a0[4], a1[4], bb0[4], bb1[4];
                    const uint32_t hbse = uHS + (uint32_t)((s * 128 + kk * 32));
                    ldsm4(a0, hbse + (uint32_t)(rbase * (LDHH * 2)) + aOffH);
                    ldsm4(a1, hbse + (uint32_t)((rbase + 16) * (LDHH * 2)) + aOffH);
                    const uint32_t bbse = uW2 + (uint32_t)(s * (128 * PITB)) + (uint32_t)(kk * 32);
                    ldsm4(bb0, bbse + (uint32_t)(cbase * PITB) + bOffT);
                    ldsm4(bb1, bbse + (uint32_t)((cbase + 16) * PITB) + bOffT);
                    mma16(&outacc[0],  a0, bb0[0], bb0[1]);
                    mma16(&outacc[4],  a0, bb0[2], bb0[3]);
                    mma16(&outacc[8],  a0, bb1[0], bb1[1]);
                    mma16(&outacc[12], a0, bb1[2], bb1[3]);
                    mma16(&outacc[16], a1, bb0[0], bb0[1]);
                    mma16(&outacc[20], a1, bb0[2], bb0[3]);
                    mma16(&outacc[24], a1, bb1[0], bb1[1]);
                    mma16(&outacc[28], a1, bb1[2], bb1[3]);
                }
            }
        } // ht
    } // experts

    // ---- epilogue: out = outacc + q @ b2 ----
#pragma unroll
    for (int tm = 0; tm < 2; tm++) {
        int r0 = rbase + tm * 16 + gr;
        float qa[K_], qb[K_];
#pragma unroll
        for (int k = 0; k < K_; k++) {
            qa[k] = g_q[(size_t)(n0 + r0) * K_ + k];
            qb[k] = g_q[(size_t)(n0 + r0 + 8) * K_ + k];
        }
#pragma unroll
        for (int tn = 0; tn < 4; tn++) {
            int idx = tm * 16 + tn * 4;
            int c0  = cbase + tn * 8 + 2 * tig;
            float v00 = outacc[idx + 0], v01 = outacc[idx + 1];
            float v10 = outacc[idx + 2], v11 = outacc[idx + 3];
#pragma unroll
            for (int k = 0; k < K_; k++) {
                v00 = fmaf(qa[k], b2s[k * C_ + c0],     v00);
                v01 = fmaf(qa[k], b2s[k * C_ + c0 + 1], v01);
                v10 = fmaf(qb[k], b2s[k * C_ + c0],     v10);
                v11 = fmaf(qb[k], b2s[k * C_ + c0 + 1], v11);
            }
            *(float2*)&out[(size_t)(n0 + r0) * C_ + c0]     = make_float2(v00, v01);
            *(float2*)&out[(size_t)(n0 + r0 + 8) * C_ + c0] = make_float2(v10, v11);
        }
    }
}

// ---------------------------------------------------------------------------
extern "C" void kernel_launch(void* const* d_in, const int* in_sizes, int n_in,
                              void* d_out, int out_size) {
    const float* z  = (const float*)d_in[0];  // [N, NZ]
    const float* mu = (const float*)d_in[1];  // [K, NZ]
    const float* W1 = (const float*)d_in[2];  // [K, NZ, H]
    const float* b1 = (const float*)d_in[3];  // [K, H]
    const float* W2 = (const float*)d_in[4];  // [K, H, C]
    const float* b2 = (const float*)d_in[5];  // [K, C]
    float* out = (float*)d_out;               // [N, C]

    cudaFuncSetAttribute(fused_mma, cudaFuncAttributeMaxDynamicSharedMemorySize, SMEM_DYN);

    prep_kernel<<<NB_Z + NB_T1 + NB_T2 + NB_Q, PREP_TPB>>>(z, mu, W1, W2);
    fused_mma<<<N_ / BM, TPB, SMEM_DYN>>>(b1, b2, out);
}